// round 16
// baseline (speedup 1.0000x reference)
#include <cuda_runtime.h>

#define BB 128
#define PP 4096
#define NN 64
#define NWORK 444   // 148 SMs x occ3 -> whole grid resident in one wave

// Split-contribution scratch (statically zero-initialized; self-resetting:
// every element receives exactly 2 contributions per launch, and the second
// contributor reads-and-zeroes it, so state is zero again after each launch).
__device__ float g_acc[BB * NN];
__device__ int   g_cnt[BB * NN];

// Persistent workers. Worker w owns center-octet g = w%8 (coeffs in registers,
// loaded ONCE) and sweeps units (b, point-half) strided across its g-pool:
// 256 units / ~55.5 workers = 4-5 units each -> ~9% makespan tail (was ~30%).
// Per unit: 8 warps x 4 iters x 2 points/lane, 16 EX2 chains/warp-iter
// (the proven R11 inner loop). occ-3/85-reg scheduling sweet spot.
// q[n](x) = K + a0*x0^2 + b0*x0 + a1*x1^2 + b1*x1,  exp(-dist) = EX2(q)
__global__ __launch_bounds__(256, 3) void slayer_persist(
    const float4* __restrict__ batch,    // [B, P/2] of float4 (2 points, D=2)
    const float2* __restrict__ mask,     // [B, P/2] of float2
    const float*  __restrict__ centers,  // [N, D]
    const float*  __restrict__ sharp,    // [N, D]
    float*        __restrict__ out)      // [B, N]
{
    const int w    = blockIdx.x;
    const int g    = w & 7;              // center octet
    const int wg   = w >> 3;             // worker index within octet pool
    const int ng   = (g < 4) ? 56 : 55;  // 444 = 8*55 + 4
    const int tid  = threadIdx.x;
    const int warp = tid >> 5;
    const int lane = tid & 31;
    const int n0   = 8 * g;

    __shared__ float partial[8][8];      // [warp][center]

    const float L = 1.4426950408889634f;  // log2(e)

    // ---- One-time prologue: coefficients for this worker's 8 centers ----
    float B0[8], B1[8], KK[8];
    float a00 = 0.0f, a10 = 0.0f;
    bool uniform = true;
#pragma unroll
    for (int j = 0; j < 8; j++) {
        const int n = n0 + j;
        const float c0 = __ldg(centers + 2 * n);
        const float c1 = __ldg(centers + 2 * n + 1);
        const float s0 = __ldg(sharp + 2 * n);
        const float s1 = __ldg(sharp + 2 * n + 1);
        const float a0 = -L * s0 * s0;
        const float a1 = -L * s1 * s1;
        if (j == 0) { a00 = a0; a10 = a1; }
        uniform = uniform && (a0 == a00) && (a1 == a10);
        B0[j] = -2.0f * a0 * c0;
        B1[j] = -2.0f * a1 * c1;
        KK[j] = a0 * c0 * c0 + a1 * c1 * c1;
    }

    if (uniform) {
        // ---- Unit sweep: unit u = (b = u>>1, half = u&1) ----
        for (int u = wg; u < BB * 2; u += ng) {
            const int b = u >> 1;
            const int h = u & 1;

            // This warp's 256-point range within the half: 128 float4.
            const float4* bp = batch + (size_t)b * (PP / 2) + h * (PP / 4)
                               + warp * 128 + lane;
            const float2* mp = mask  + (size_t)b * (PP / 2) + h * (PP / 4)
                               + warp * 128 + lane;

            float acc[8];
#pragma unroll
            for (int j = 0; j < 8; j++) acc[j] = 0.0f;

#pragma unroll
            for (int it = 0; it < 4; it++) {
                const float4 x = __ldg(bp + it * 32);  // A=(x,y), B=(z,w)
                const float2 m = __ldg(mp + it * 32);

                const float basea = fmaf(a00 * x.x, x.x, (a10 * x.y) * x.y);
                const float baseb = fmaf(a00 * x.z, x.z, (a10 * x.w) * x.w);

#pragma unroll
                for (int j = 0; j < 8; j++) {
                    float qa = fmaf(B0[j], x.x, KK[j]);
                    qa = fmaf(B1[j], x.y, qa);
                    qa += basea;
                    float qb = fmaf(B0[j], x.z, KK[j]);
                    qb = fmaf(B1[j], x.w, qb);
                    qb += baseb;
                    float ea, eb;
                    asm("ex2.approx.ftz.f32 %0, %1;" : "=f"(ea) : "f"(qa));
                    asm("ex2.approx.ftz.f32 %0, %1;" : "=f"(eb) : "f"(qb));
                    acc[j] = fmaf(m.x, ea, acc[j]);
                    acc[j] = fmaf(m.y, eb, acc[j]);
                }
            }

            // Lane reduce -> warp partials -> block sum -> split-K combine
#pragma unroll
            for (int off = 16; off > 0; off >>= 1) {
#pragma unroll
                for (int j = 0; j < 8; j++)
                    acc[j] += __shfl_xor_sync(0xffffffffu, acc[j], off);
            }
            if (lane == 0) {
#pragma unroll
                for (int j = 0; j < 8; j++)
                    partial[warp][j] = acc[j];
            }
            __syncthreads();

            if (tid < 8) {
                float v = 0.0f;
#pragma unroll
                for (int wp = 0; wp < 8; wp++)
                    v += partial[wp][tid];
                const int idx = b * NN + n0 + tid;
                atomicAdd(&g_acc[idx], v);
                __threadfence();
                const int old = atomicAdd(&g_cnt[idx], 1);
                if (old == 1) {   // second (last) contributor
                    __threadfence();
                    const float r = atomicExch(&g_acc[idx], 0.0f); // read+reset
                    out[idx] = r;
                    atomicExch(&g_cnt[idx], 0);                    // reset
                }
            }
            __syncthreads();   // protect partial[] reuse next unit
        }
    } else {
        // ---- General path (cold): full per-center quadratic ----
        float A0g[8], A1g[8];
#pragma unroll
        for (int j = 0; j < 8; j++) {
            const int n = n0 + j;
            const float s0 = __ldg(sharp + 2 * n);
            const float s1 = __ldg(sharp + 2 * n + 1);
            A0g[j] = -L * s0 * s0;
            A1g[j] = -L * s1 * s1;
        }
        for (int u = wg; u < BB * 2; u += ng) {
            const int b = u >> 1;
            const int h = u & 1;
            const float4* bp = batch + (size_t)b * (PP / 2) + h * (PP / 4)
                               + warp * 128 + lane;
            const float2* mp = mask  + (size_t)b * (PP / 2) + h * (PP / 4)
                               + warp * 128 + lane;

            float acc[8];
#pragma unroll
            for (int j = 0; j < 8; j++) acc[j] = 0.0f;

#pragma unroll 2
            for (int it = 0; it < 4; it++) {
                const float4 x = __ldg(bp + it * 32);
                const float2 m = __ldg(mp + it * 32);
                const float xa0 = x.x * x.x, xa1 = x.y * x.y;
                const float xb0 = x.z * x.z, xb1 = x.w * x.w;
#pragma unroll
                for (int j = 0; j < 8; j++) {
                    float qa = KK[j];
                    qa = fmaf(A0g[j], xa0, qa);
                    qa = fmaf(B0[j], x.x, qa);
                    qa = fmaf(A1g[j], xa1, qa);
                    qa = fmaf(B1[j], x.y, qa);
                    float qb = KK[j];
                    qb = fmaf(A0g[j], xb0, qb);
                    qb = fmaf(B0[j], x.z, qb);
                    qb = fmaf(A1g[j], xb1, qb);
                    qb = fmaf(B1[j], x.w, qb);
                    float ea, eb;
                    asm("ex2.approx.ftz.f32 %0, %1;" : "=f"(ea) : "f"(qa));
                    asm("ex2.approx.ftz.f32 %0, %1;" : "=f"(eb) : "f"(qb));
                    acc[j] = fmaf(m.x, ea, acc[j]);
                    acc[j] = fmaf(m.y, eb, acc[j]);
                }
            }

#pragma unroll
            for (int off = 16; off > 0; off >>= 1) {
#pragma unroll
                for (int j = 0; j < 8; j++)
                    acc[j] += __shfl_xor_sync(0xffffffffu, acc[j], off);
            }
            if (lane == 0) {
#pragma unroll
                for (int j = 0; j < 8; j++)
                    partial[warp][j] = acc[j];
            }
            __syncthreads();

            if (tid < 8) {
                float v = 0.0f;
#pragma unroll
                for (int wp = 0; wp < 8; wp++)
                    v += partial[wp][tid];
                const int idx = b * NN + n0 + tid;
                atomicAdd(&g_acc[idx], v);
                __threadfence();
                const int old = atomicAdd(&g_cnt[idx], 1);
                if (old == 1) {
                    __threadfence();
                    const float r = atomicExch(&g_acc[idx], 0.0f);
                    out[idx] = r;
                    atomicExch(&g_cnt[idx], 0);
                }
            }
            __syncthreads();
        }
    }
}

extern "C" void kernel_launch(void* const* d_in, const int* in_sizes, int n_in,
                              void* d_out, int out_size) {
    const float* batch   = (const float*)d_in[0];   // [B,P,D] f32
    const float* mask    = (const float*)d_in[1];   // [B,P]   f32
    const float* centers = (const float*)d_in[2];   // [N,D]   f32
    const float* sharp   = (const float*)d_in[3];   // [N,D]   f32
    float* out = (float*)d_out;                     // [B,N]   f32

    slayer_persist<<<NWORK, 256>>>((const float4*)batch, (const float2*)mask,
                                   centers, sharp, out);
}

// round 17
// speedup vs baseline: 1.3936x; 1.3936x over previous
#include <cuda_runtime.h>

#define BB 128
#define PP 4096
#define NN 64

// One fused kernel. Block = (batch b, center-octet g): 256 threads = 8 warps.
// Each warp sweeps its own 512-point range for the SAME 8 centers
// (coeffs register-resident), 2 points/lane/iter -> 16 EX2 chains/warp-iter.
// grid = 1024; __launch_bounds__(256,3) -> occ-3/85-reg sweet spot (R11 core).
// R17: instruction diet on prologue (lane-parallel coeffs + shfl broadcast)
// and epilogue (smem reduce instead of 5-round shfl butterfly).
// q[n](x) = K + a0*x0^2 + b0*x0 + a1*x1^2 + b1*x1,  exp(-dist) = EX2(q)
// Uniform fast path (all 8 centers share a0,a1):
//   q = (K_n + B0_n*x0 + B1_n*x1) + base(x),  base = a0*x0^2 + a1*x1^2
__global__ __launch_bounds__(256, 3) void slayer_fused(
    const float4* __restrict__ batch,    // [B, P/2] of float4 (2 points, D=2)
    const float2* __restrict__ mask,     // [B, P/2] of float2
    const float*  __restrict__ centers,  // [N, D]
    const float*  __restrict__ sharp,    // [N, D]
    float*        __restrict__ out)      // [B, N]
{
    const int b    = blockIdx.x >> 3;
    const int g    = blockIdx.x & 7;     // centers [8g, 8g+8)
    const int tid  = threadIdx.x;
    const int warp = tid >> 5;
    const int lane = tid & 31;
    const int n0   = 8 * g;

    // [warp][center][lane] raw accumulators; +1 pad kills stage-1 conflicts
    __shared__ float red[8][8][33];
    __shared__ float red2[8][8];         // [center][warp]

    const float L = 1.4426950408889634f;  // log2(e)

    // ---- Lane-parallel prologue: lane j < 8 computes center n0+j ----
    float myA0 = 0.0f, myA1 = 0.0f, myB0 = 0.0f, myB1 = 0.0f, myK = 0.0f;
    if (lane < 8) {
        const int n = n0 + lane;
        const float c0 = __ldg(centers + 2 * n);
        const float c1 = __ldg(centers + 2 * n + 1);
        const float s0 = __ldg(sharp + 2 * n);
        const float s1 = __ldg(sharp + 2 * n + 1);
        myA0 = -L * s0 * s0;
        myA1 = -L * s1 * s1;
        myB0 = -2.0f * myA0 * c0;
        myB1 = -2.0f * myA1 * c1;
        myK  = myA0 * c0 * c0 + myA1 * c1 * c1;
    }
    const float a00 = __shfl_sync(0xffffffffu, myA0, 0);
    const float a10 = __shfl_sync(0xffffffffu, myA1, 0);
    const bool lane_ok = (lane >= 8) || ((myA0 == a00) && (myA1 == a10));
    const bool uniform = __all_sync(0xffffffffu, lane_ok);

    float B0[8], B1[8], KK[8], acc[8];
#pragma unroll
    for (int j = 0; j < 8; j++) {
        B0[j] = __shfl_sync(0xffffffffu, myB0, j);
        B1[j] = __shfl_sync(0xffffffffu, myB1, j);
        KK[j] = __shfl_sync(0xffffffffu, myK,  j);
        acc[j] = 0.0f;
    }

    // This warp's 512-point range: 256 float4 entries.
    const float4* bp = batch + (size_t)b * (PP / 2) + warp * 256 + lane;
    const float2* mp = mask  + (size_t)b * (PP / 2) + warp * 256 + lane;

    constexpr int ITERS = 8;   // 8 iters x 32 lanes x 2 points = 512 points

    if (uniform) {
#pragma unroll
        for (int it = 0; it < ITERS; it++) {
            const float4 x = __ldg(bp + it * 32);  // A=(x,y), B=(z,w)
            const float2 m = __ldg(mp + it * 32);

            const float basea = fmaf(a00 * x.x, x.x, (a10 * x.y) * x.y);
            const float baseb = fmaf(a00 * x.z, x.z, (a10 * x.w) * x.w);

#pragma unroll
            for (int j = 0; j < 8; j++) {
                float qa = fmaf(B0[j], x.x, KK[j]);
                qa = fmaf(B1[j], x.y, qa);
                qa += basea;
                float qb = fmaf(B0[j], x.z, KK[j]);
                qb = fmaf(B1[j], x.w, qb);
                qb += baseb;
                float ea, eb;
                asm("ex2.approx.ftz.f32 %0, %1;" : "=f"(ea) : "f"(qa));
                asm("ex2.approx.ftz.f32 %0, %1;" : "=f"(eb) : "f"(qb));
                acc[j] = fmaf(m.x, ea, acc[j]);
                acc[j] = fmaf(m.y, eb, acc[j]);
            }
        }
    } else {
        // General path (cold): full per-center quadratic.
        float A0g[8], A1g[8];
#pragma unroll
        for (int j = 0; j < 8; j++) {
            A0g[j] = __shfl_sync(0xffffffffu, myA0, j);
            A1g[j] = __shfl_sync(0xffffffffu, myA1, j);
        }
#pragma unroll 2
        for (int it = 0; it < ITERS; it++) {
            const float4 x = __ldg(bp + it * 32);
            const float2 m = __ldg(mp + it * 32);
            const float xa0 = x.x * x.x, xa1 = x.y * x.y;
            const float xb0 = x.z * x.z, xb1 = x.w * x.w;
#pragma unroll
            for (int j = 0; j < 8; j++) {
                float qa = KK[j];
                qa = fmaf(A0g[j], xa0, qa);
                qa = fmaf(B0[j], x.x, qa);
                qa = fmaf(A1g[j], xa1, qa);
                qa = fmaf(B1[j], x.y, qa);
                float qb = KK[j];
                qb = fmaf(A0g[j], xb0, qb);
                qb = fmaf(B0[j], x.z, qb);
                qb = fmaf(A1g[j], xb1, qb);
                qb = fmaf(B1[j], x.w, qb);
                float ea, eb;
                asm("ex2.approx.ftz.f32 %0, %1;" : "=f"(ea) : "f"(qa));
                asm("ex2.approx.ftz.f32 %0, %1;" : "=f"(eb) : "f"(qb));
                acc[j] = fmaf(m.x, ea, acc[j]);
                acc[j] = fmaf(m.y, eb, acc[j]);
            }
        }
    }

    // ---- Smem epilogue: no shfl butterfly ----
    // Stage 0: every lane stores its 8 raw accumulators (conflict-free).
#pragma unroll
    for (int j = 0; j < 8; j++)
        red[warp][j][lane] = acc[j];
    __syncthreads();

    // Stage 1: 64 threads; thread (w = t>>3, j = t&7) sums 32 lanes.
    // Row stride 33 -> each fixed k hits 32 distinct banks.
    if (tid < 64) {
        const int w = tid >> 3;
        const int j = tid & 7;
        float s = 0.0f;
#pragma unroll
        for (int k = 0; k < 32; k++)
            s += red[w][j][k];
        red2[j][w] = s;
    }
    __syncthreads();

    // Stage 2: 8 threads finish across warps and store.
    if (tid < 8) {
        float v = 0.0f;
#pragma unroll
        for (int w = 0; w < 8; w++)
            v += red2[tid][w];
        out[b * NN + n0 + tid] = v;
    }
}

extern "C" void kernel_launch(void* const* d_in, const int* in_sizes, int n_in,
                              void* d_out, int out_size) {
    const float* batch   = (const float*)d_in[0];   // [B,P,D] f32
    const float* mask    = (const float*)d_in[1];   // [B,P]   f32
    const float* centers = (const float*)d_in[2];   // [N,D]   f32
    const float* sharp   = (const float*)d_in[3];   // [N,D]   f32
    float* out = (float*)d_out;                     // [B,N]   f32

    slayer_fused<<<BB * 8, 256>>>((const float4*)batch, (const float2*)mask,
                                  centers, sharp, out);
}